// round 16
// baseline (speedup 1.0000x reference)
#include <cuda_runtime.h>
#include <math.h>

#define BATCH 64
#define NPTS 1024
#define NT 128
#define PPT 8               // points per thread per cloud (NT*PPT == NPTS)
#define NWARPS 4
#define KMASK 0xFFFFFC00u   // top 22 bits of d2, low 10 bits = point index

__device__ float g_partial[BATCH];

#define PACK2(out, lo, hi) \
    asm("mov.b64 %0, {%1, %2};" : "=l"(out) : "f"(lo), "f"(hi))
#define UNPACK2(lo, hi, in) \
    asm("mov.b64 {%0, %1}, %2;" : "=f"(lo), "=f"(hi) : "l"(in))
#define FMA2(out, a, b, c) \
    asm("fma.rn.f32x2 %0, %1, %2, %3;" : "=l"(out) : "l"(a), "l"(b), "l"(c))
#define ADD2(out, a, b) \
    asm("add.rn.f32x2 %0, %1, %2;" : "=l"(out) : "l"(a), "l"(b))

union F2U { float2 f; unsigned long long u; };

// One CTA handles BOTH clouds of one batch (gts[b] and preds[b]), interleaving
// their Prim iterations so one barrier/sync-chain serves two MST extractions.
__global__ __launch_bounds__(NT, 1)
void prim_kernel(const float* __restrict__ gts, const float* __restrict__ preds) {
    const int b = blockIdx.x;  // 0..63

    // Arena: [sp4A 16KB][sp4B 16KB][scratch 12KB: raw, later sbits/sdeath A+B]
    __shared__ __align__(16) char arena[2 * NPTS * 16 + NPTS * 12];
    float4* const sp4[2] = { (float4*)arena, (float4*)(arena + NPTS * 16) };
    float* const raw = (float*)(arena + 2 * NPTS * 16);
    unsigned* const sbits[2] = { (unsigned*)(arena + 2 * NPTS * 16),
                                 (unsigned*)(arena + 2 * NPTS * 16) + NPTS };
    float* const sdeath[2] = { (float*)sbits[0], (float*)sbits[1] };
    __shared__ __align__(16) unsigned swarp[2][2][NWARPS];  // [cloud][buffer][warp]

    const int t = threadIdx.x;
    const int lane = t & 31;
    const int wid = t >> 5;
    const unsigned idx0 = (unsigned)(t * PPT);

    // Per-cloud register state: (-2x,-2y,-2z) packed f32x2; |p|^2 packed; d2 scalar.
    unsigned long long mx2[2][PPT / 2], my2[2][PPT / 2], mz2[2][PPT / 2];
    F2U sq2[2][PPT / 2];
    float d2[2][PPT];

    // Sequential init of the two clouds through the shared raw buffer.
    const float* const bases[2] = { gts + (size_t)b * NPTS * 3,
                                    preds + (size_t)b * NPTS * 3 };
#pragma unroll
    for (int c = 0; c < 2; c++) {
        for (int i = t; i < NPTS * 3; i += NT) raw[i] = bases[c][i];
        __syncthreads();
        const float x0 = raw[0], y0 = raw[1], z0 = raw[2];
        const float w0 = fmaf(x0, x0, fmaf(y0, y0, z0 * z0));
        float ax[PPT], ay[PPT], az[PPT], aw[PPT];
#pragma unroll
        for (int k = 0; k < PPT; k++) {
            const int i = t * PPT + k;
            const float x = raw[i * 3 + 0], y = raw[i * 3 + 1], z = raw[i * 3 + 2];
            const float w = fmaf(x, x, fmaf(y, y, z * z));
            ax[k] = x; ay[k] = y; az[k] = z; aw[k] = w;
            sp4[c][i] = make_float4(x, y, z, w);
            // Gram form, matching the reference: d2 = |p|^2+|p0|^2-2p.p0, clamp >= 0
            const float dd = fmaf(-2.0f * x, x0,
                             fmaf(-2.0f * y, y0, fmaf(-2.0f * z, z0, w + w0)));
            d2[c][k] = fmaxf(dd, 0.0f);
        }
#pragma unroll
        for (int p = 0; p < PPT / 2; p++) {
            PACK2(mx2[c][p], -2.0f * ax[2 * p], -2.0f * ax[2 * p + 1]);
            PACK2(my2[c][p], -2.0f * ay[2 * p], -2.0f * ay[2 * p + 1]);
            PACK2(mz2[c][p], -2.0f * az[2 * p], -2.0f * az[2 * p + 1]);
            sq2[c][p].f = make_float2(aw[2 * p], aw[2 * p + 1]);
        }
        if (t == 0) { d2[c][0] = 1e30f; sq2[c][0].f.x = 1e30f; }  // point 0 joined
        __syncthreads();  // raw dead before next cloud overwrites it
    }

    // Winner keys buffered in registers; sbits aliases raw, so stores are deferred
    // to after the loop? No -- raw is already dead; sbits writes are safe now.
#pragma unroll 2
    for (int it = 0; it < NPTS - 1; it++) {
        // Both clouds' argmins: pack keys, local min, one REDUX each (latencies overlap).
        unsigned key[2];
#pragma unroll
        for (int c = 0; c < 2; c++) {
            unsigned cc[PPT];
#pragma unroll
            for (int k = 0; k < PPT; k++)
                cc[k] = (__float_as_uint(d2[c][k]) & KMASK) | (idx0 + (unsigned)k);
            unsigned km = min(min(min(cc[0], cc[1]), min(cc[2], cc[3])),
                              min(min(cc[4], cc[5]), min(cc[6], cc[7])));
            key[c] = __reduce_min_sync(0xffffffffu, km);
        }
        if (lane == 0) {
            swarp[0][it & 1][wid] = key[0];
            swarp[1][it & 1][wid] = key[1];
        }
        __syncthreads();

#pragma unroll
        for (int c = 0; c < 2; c++) {
            const uint4 a = *(const uint4*)&swarp[c][it & 1][0];
            const unsigned best = min(min(a.x, a.y), min(a.z, a.w));
            const int j = (int)(best & 1023u);
            if (t == 0) sbits[c][it] = best;  // sqrt deferred out of the loop

            const float4 pj = sp4[c][j];      // one LDS.128 broadcast
            const int rel = j - (int)idx0;
            unsigned long long pjx2, pjy2, pjz2, pjw2;
            PACK2(pjx2, pj.x, pj.x);
            PACK2(pjy2, pj.y, pj.y);
            PACK2(pjz2, pj.z, pj.z);
            PACK2(pjw2, pj.w, pj.w);
#pragma unroll
            for (int p = 0; p < PPT / 2; p++) {
                unsigned long long s2, acc;
                ADD2(s2, sq2[c][p].u, pjw2);
                FMA2(acc, mx2[c][p], pjx2, s2);
                FMA2(acc, my2[c][p], pjy2, acc);
                FMA2(acc, mz2[c][p], pjz2, acc);
                float lo, hi;
                UNPACK2(lo, hi, acc);
                // No clamp: cancellation error (~1e-6) << min true d2 (~1e-4).
                d2[c][2 * p]     = fminf(d2[c][2 * p],     lo);
                d2[c][2 * p + 1] = fminf(d2[c][2 * p + 1], hi);
            }
#pragma unroll
            for (int p = 0; p < PPT / 2; p++) {
                if (rel == 2 * p)     { d2[c][2 * p]     = 1e30f; sq2[c][p].f.x = 1e30f; }
                if (rel == 2 * p + 1) { d2[c][2 * p + 1] = 1e30f; sq2[c][p].f.y = 1e30f; }
            }
        }
        // no second barrier: swarp is double-buffered
    }

    __syncthreads();
    // Packed winner bits -> death values (strip the 10 index bits), both clouds.
    for (int i = t; i < NPTS - 1; i += NT) {
        sdeath[0][i] = sqrtf(__uint_as_float(sbits[0][i] & KMASK) + 1e-12f);
        sdeath[1][i] = sqrtf(__uint_as_float(sbits[1][i] & KMASK) + 1e-12f);
    }
    if (t == 0) {
        sdeath[0][NPTS - 1] = __int_as_float(0x7f800000);
        sdeath[1][NPTS - 1] = __int_as_float(0x7f800000);
    }
    // Bitonic sort both arrays ascending (same schedule, two CAS per index).
    for (int k = 2; k <= NPTS; k <<= 1) {
        for (int j = k >> 1; j > 0; j >>= 1) {
            __syncthreads();
            for (int i = t; i < NPTS; i += NT) {
                const int ixj = i ^ j;
                if (ixj > i) {
                    const bool up = ((i & k) == 0);
                    float va = sdeath[0][i], vb = sdeath[0][ixj];
                    if ((va > vb) == up) { sdeath[0][i] = vb; sdeath[0][ixj] = va; }
                    va = sdeath[1][i]; vb = sdeath[1][ixj];
                    if ((va > vb) == up) { sdeath[1][i] = vb; sdeath[1][ixj] = va; }
                }
            }
        }
    }
    __syncthreads();

    // In-block W1 partial: sum |sorted_A - sorted_B| over the N-1 real deaths.
    float s = 0.0f;
    for (int i = t; i < NPTS - 1; i += NT)
        s += fabsf(sdeath[0][i] - sdeath[1][i]);
    __shared__ float red[NWARPS];
#pragma unroll
    for (int off = 16; off; off >>= 1) s += __shfl_down_sync(0xffffffffu, s, off);
    if (lane == 0) red[wid] = s;
    __syncthreads();
    if (t == 0) g_partial[b] = red[0] + red[1] + red[2] + red[3];
}

__global__ void wloss_final(float* __restrict__ out) {
    const int t = threadIdx.x;  // 32 threads
    float v = g_partial[t] + g_partial[t + 32];
#pragma unroll
    for (int off = 16; off; off >>= 1) v += __shfl_down_sync(0xffffffffu, v, off);
    if (t == 0) *out = v * (1.0f / BATCH);  // TOPO_LAMBDA = 1.0
}

extern "C" void kernel_launch(void* const* d_in, const int* in_sizes, int n_in,
                              void* d_out, int out_size) {
    const float* gts = (const float*)d_in[0];
    const float* preds = (const float*)d_in[1];
    float* out = (float*)d_out;
    prim_kernel<<<BATCH, NT>>>(gts, preds);
    wloss_final<<<1, 32>>>(out);
}